// round 6
// baseline (speedup 1.0000x reference)
#include <cuda_runtime.h>
#include <cuda_bf16.h>
#include <cstdint>

// out[i,j,o] = sum_h x[i+1,h]*x[j+1,h]*W[o,h] + b[o]
// (diff/W2 term is antisymmetric -> cancels under (P+P^T)/2 symmetrization)
//
// D_o = A_o B^T, A_o = X .* w_o, B = X (512x768 f32)
// fp32 emulated via bf16 hi/lo 3-split on mma.sync m16n8k16.
// Upper-tri 32x32 tiles (mirror-write), split-K=3 via red.global.add onto
// zeroed buffer (exactly 3 commutative adds per element -> deterministic).

#define HDIM 768
#define KC 64                    // k per chunk (64 bf16 = 128 B rows)
#define KSPLIT 3
#define NKC 4                    // chunks per K-split (12 total / 3)
#define ROW_B 144                // 128 B data + 16 B pad (conflict-free LDSM)
#define TILE_B (32 * ROW_B)      // 4608 B  (32 rows x 64 bf16)
#define STAGE_B (4 * TILE_B)     // Ahi, Alo, Bhi, Blo = 18432 B
#define NSTAGE 2
#define SMEM_TOTAL (NSTAGE * STAGE_B)   // 36864 B -> 6 CTAs/SM
#define OUT_ELEMS (510 * 510 * 2)

// Pre-split bf16 images: 0:A0hi 1:A0lo 2:A1hi 3:A1lo 4:Bhi 5:Blo
__device__ __nv_bfloat16 g_pre[6][512 * HDIM];

// ---------------------------------------------------------------------------
union Pack8 { __nv_bfloat16 h[8]; uint4 v; };

__device__ __forceinline__ void split8(const float* s, uint4& hi, uint4& lo) {
    Pack8 ph, pl;
#pragma unroll
    for (int t = 0; t < 8; t++) {
        __nv_bfloat16 h = __float2bfloat16(s[t]);
        ph.h[t] = h;
        pl.h[t] = __float2bfloat16(s[t] - __bfloat162float(h));
    }
    hi = ph.v; lo = pl.v;
}

__global__ void prep_kernel(const float* __restrict__ x,
                            const float* __restrict__ W,
                            float* __restrict__ out)
{
    int gid = blockIdx.x * blockDim.x + threadIdx.x;

    // Zero the output buffer (fp32 reductions accumulate into it)
    if (gid < OUT_ELEMS / 4)
        *(float4*)(out + (size_t)gid * 4) = make_float4(0.f, 0.f, 0.f, 0.f);
    // tail elements (510*510*2 = 520200 -> /4 = 130050 exact, no tail)

    if (gid >= 512 * (HDIM / 8)) return;
    int i  = gid / (HDIM / 8);
    int k0 = (gid % (HDIM / 8)) * 8;

    float4 x0 = *(const float4*)(x + (size_t)i * HDIM + k0);
    float4 x1 = *(const float4*)(x + (size_t)i * HDIM + k0 + 4);
    float4 wa0 = *(const float4*)(W + k0);
    float4 wa1 = *(const float4*)(W + k0 + 4);
    float4 wb0 = *(const float4*)(W + 1536 + k0);
    float4 wb1 = *(const float4*)(W + 1536 + k0 + 4);

    float xs[8] = {x0.x, x0.y, x0.z, x0.w, x1.x, x1.y, x1.z, x1.w};
    float w0[8] = {wa0.x, wa0.y, wa0.z, wa0.w, wa1.x, wa1.y, wa1.z, wa1.w};
    float w1[8] = {wb0.x, wb0.y, wb0.z, wb0.w, wb1.x, wb1.y, wb1.z, wb1.w};
    float a0[8], a1[8];
#pragma unroll
    for (int t = 0; t < 8; t++) { a0[t] = xs[t] * w0[t]; a1[t] = xs[t] * w1[t]; }

    uint4 h, l;
    size_t off = (size_t)i * HDIM + k0;
    split8(a0, h, l);
    *(uint4*)(&g_pre[0][off]) = h;  *(uint4*)(&g_pre[1][off]) = l;
    split8(a1, h, l);
    *(uint4*)(&g_pre[2][off]) = h;  *(uint4*)(&g_pre[3][off]) = l;
    split8(xs, h, l);
    *(uint4*)(&g_pre[4][off]) = h;  *(uint4*)(&g_pre[5][off]) = l;
}

// ---------------------------------------------------------------------------
__device__ __forceinline__ uint32_t smem_u32(const void* p) {
    uint32_t a;
    asm("{ .reg .u64 t; cvta.to.shared.u64 t, %1; cvt.u32.u64 %0, t; }"
        : "=r"(a) : "l"(p));
    return a;
}

__device__ __forceinline__ void cp16(uint32_t dst, const void* src) {
    asm volatile("cp.async.cg.shared.global [%0], [%1], 16;"
                 :: "r"(dst), "l"(src) : "memory");
}

__device__ __forceinline__ void ldsm4(uint32_t* r, uint32_t addr) {
    asm volatile("ldmatrix.sync.aligned.m8n8.x4.shared.b16 {%0,%1,%2,%3}, [%4];"
                 : "=r"(r[0]), "=r"(r[1]), "=r"(r[2]), "=r"(r[3]) : "r"(addr));
}

__device__ __forceinline__ void mma16816(float* c, const uint32_t* a,
                                         uint32_t b0, uint32_t b1) {
    asm volatile(
        "mma.sync.aligned.m16n8k16.row.col.f32.bf16.bf16.f32 "
        "{%0,%1,%2,%3}, {%4,%5,%6,%7}, {%8,%9}, {%0,%1,%2,%3};"
        : "+f"(c[0]), "+f"(c[1]), "+f"(c[2]), "+f"(c[3])
        : "r"(a[0]), "r"(a[1]), "r"(a[2]), "r"(a[3]), "r"(b0), "r"(b1));
}

__device__ __forceinline__ void red_add(float* p, float v) {
    asm volatile("red.global.add.f32 [%0], %1;" :: "l"(p), "f"(v) : "memory");
}

__global__ void __launch_bounds__(128)
pairwise_mma_kernel(const float* __restrict__ bias, float* __restrict__ out)
{
    // Triangular decode: blockIdx.x in [0,136) -> (bi, bj), bj >= bi
    int t = blockIdx.x;
    int bi = 0;
    while (t >= 16 - bi) { t -= 16 - bi; bi++; }
    const int bj = bi + t;
    const int ch = blockIdx.y;
    const int ks = blockIdx.z;          // K split (0..2)

    extern __shared__ __align__(16) char smem[];
    const uint32_t sb = smem_u32(smem);

    const int tid  = threadIdx.x;
    const int wid  = tid >> 5;
    const int lane = tid & 31;
    const int wm = wid >> 1;          // warp row (0..1) of 16
    const int wn = wid & 1;           // warp col (0..1) of 16

    const __nv_bfloat16* src[4];
    src[0] = &g_pre[ch * 2 + 0][(size_t)(bi * 32) * HDIM];
    src[1] = &g_pre[ch * 2 + 1][(size_t)(bi * 32) * HDIM];
    src[2] = &g_pre[4][(size_t)(bj * 32) * HDIM];
    src[3] = &g_pre[5][(size_t)(bj * 32) * HDIM];

    const int lrow = tid >> 3;        // 0..15
    const int lc   = tid & 7;         // 16B chunk within 128B row
    const int kc0  = ks * NKC;        // first chunk of this split

    auto issue = [&](int kc, int sl) {
        const uint32_t dbase = sb + sl * STAGE_B + lc * 16;
        const int kcol = (kc0 + kc) * KC + lc * 8;
#pragma unroll
        for (int q = 0; q < 4; q++) {
#pragma unroll
            for (int p = 0; p < 2; p++) {
                const int row = lrow + p * 16;
                cp16(dbase + q * TILE_B + row * ROW_B,
                     src[q] + (size_t)row * HDIM + kcol);
            }
        }
    };

    // Three independent split chains: 0=hh, 1=hl, 2=lh
    float acc[3][2][4] = {};

    const uint32_t arow = (uint32_t)(wm * 16 + (lane & 15)) * ROW_B
                        + ((lane >> 4) << 4);
    const uint32_t brow = (uint32_t)(wn * 16 + (lane & 15)) * ROW_B
                        + ((lane >> 4) << 4);

    auto compute = [&](int sl) {
        const uint32_t tb = sb + sl * STAGE_B;
#pragma unroll
        for (int h = 0; h < 4; h++) {           // four k16 slices of k64
            uint32_t ah[4], al[4], bh[4], bl[4];
            ldsm4(ah, tb + 0 * TILE_B + arow + h * 32);
            ldsm4(al, tb + 1 * TILE_B + arow + h * 32);
            ldsm4(bh, tb + 2 * TILE_B + brow + h * 32);
            ldsm4(bl, tb + 3 * TILE_B + brow + h * 32);
#pragma unroll
            for (int nf = 0; nf < 2; nf++) {
                mma16816(acc[0][nf], ah, bh[nf], bh[nf + 2]);
                mma16816(acc[1][nf], ah, bl[nf], bl[nf + 2]);
                mma16816(acc[2][nf], al, bh[nf], bh[nf + 2]);
            }
        }
    };

    // ---- 2-stage cp.async pipeline over 4 chunks ----
    issue(0, 0);
    asm volatile("cp.async.commit_group;" ::: "memory");
    issue(1, 1);
    asm volatile("cp.async.commit_group;" ::: "memory");

#pragma unroll 1
    for (int kc = 0; kc < NKC; kc++) {
        if (kc < NKC - 1)
            asm volatile("cp.async.wait_group 1;" ::: "memory");
        else
            asm volatile("cp.async.wait_group 0;" ::: "memory");
        __syncthreads();
        compute(kc & 1);
        __syncthreads();
        if (kc + 2 < NKC) {
            issue(kc + 2, kc & 1);
            asm volatile("cp.async.commit_group;" ::: "memory");
        }
    }

    // ---- epilogue: bias/3 per split, crop [1,510], mirror, red.add ----
    const float bv = bias[ch] * (1.0f / 3.0f);
    const int ib = bi * 32 + wm * 16;
    const int jb = bj * 32 + wn * 16;
    const bool mirror = (bi != bj);

#pragma unroll
    for (int nf = 0; nf < 2; nf++) {
#pragma unroll
        for (int r = 0; r < 4; r++) {
            const int i = ib + (lane >> 2) + ((r >> 1) << 3);
            const int j = jb + nf * 8 + ((lane & 3) << 1) + (r & 1);
            if (i >= 1 && i <= 510 && j >= 1 && j <= 510) {
                const float v = acc[0][nf][r] + acc[1][nf][r]
                              + acc[2][nf][r] + bv;
                red_add(out + ((size_t)(i - 1) * 510 + (j - 1)) * 2 + ch, v);
                if (mirror)
                    red_add(out + ((size_t)(j - 1) * 510 + (i - 1)) * 2 + ch, v);
            }
        }
    }
}

// ---------------------------------------------------------------------------
extern "C" void kernel_launch(void* const* d_in, const int* in_sizes, int n_in,
                              void* d_out, int out_size)
{
    const float* x = (const float*)d_in[0];   // (1, 512, 768)
    const float* W = (const float*)d_in[1];   // (2, 1536)
    const float* b = (const float*)d_in[2];   // (2,)
    float* out = (float*)d_out;               // (510, 510, 2)

    cudaFuncSetAttribute(pairwise_mma_kernel,
                         cudaFuncAttributeMaxDynamicSharedMemorySize, SMEM_TOTAL);

    prep_kernel<<<(OUT_ELEMS / 4 + 255) / 256, 256>>>(x, W, out);
    pairwise_mma_kernel<<<dim3(136, 2, KSPLIT), 128, SMEM_TOTAL>>>(b, out);
}